// round 14
// baseline (speedup 1.0000x reference)
#include <cuda_runtime.h>
#include <cuda_fp16.h>
#include <cstdint>
#include <cstddef>

// Problem constants
#define NEMB   1024
#define EDIM   256
#define BATCH  8
#define HWL    4096
#define NROWS  32768
#define MT     128
#define NBLK   256
#define NCHK   16            // 16 chunks of 64 codes
#define CAP    8192

// smem byte offsets
#define SM_A     0           // 128 rows * 36 uint4 = 73728 B (skewed)
#define SM_B     73728       // 2 * (32 d8-rows * 65 uint4 * 16B) = 66560 B
#define BBYTES   33280
#define SM_E2    140288      // 2*64 floats
#define SM_Z2    140800
#define SM_CR    141312
#define SM_EP    141824
#define SM_V     142336      // 2*128 floats
#define SM_BEST  143360      // 128 u64
#define SM_CAND  144384      // 8192 u32
#define SM_CNT   177152
#define SM_TOTAL 177168

// Scratch
__device__ float  g_zf[NROWS*EDIM];   // z transposed (N, D) fp32
__device__ uint4  g_zh[NROWS*32];     // fp16 zhat rows (32 uint4 = 256 dims)
__device__ uint4  g_eh[NEMB*32];      // fp16 ehat rows (e * 1024)
__device__ float  g_e2[NEMB];
__device__ float  g_z2[NROWS];
__device__ float  g_cr[NROWS];        // amax/512
__device__ float  g_eps[NROWS];       // generous screening window
__device__ int    g_idx[NROWS];
__device__ double g_partial[NBLK];

// ---------------- helpers ----------------
__device__ __forceinline__ uint32_t smem_u32(const void* p) {
    uint32_t a;
    asm("{ .reg .u64 t; cvta.to.shared.u64 t, %1; cvt.u32.u64 %0, t; }" : "=r"(a) : "l"(p));
    return a;
}
__device__ __forceinline__ void cpa16(uint32_t dst, const void* src) {
    asm volatile("cp.async.cg.shared.global [%0], [%1], 16;" :: "r"(dst), "l"(src));
}
__device__ __forceinline__ void cpa4(uint32_t dst, const void* src) {
    asm volatile("cp.async.ca.shared.global [%0], [%1], 4;" :: "r"(dst), "l"(src));
}
#define CP_COMMIT() asm volatile("cp.async.commit_group;" ::: "memory")
#define CP_WAIT1()  asm volatile("cp.async.wait_group 1;" ::: "memory")
#define CP_WAIT0()  asm volatile("cp.async.wait_group 0;" ::: "memory")

// injective code placement within a 64-code chunk (bijection on [0,64))
__device__ __forceinline__ int bpos(int c) { return c ^ ((c >> 3) & 7); }

// exact fp32 distance — IDENTICAL pipeline to the passing R2/R7/R11 kernels
__device__ __forceinline__ float exact_dist(int nrow, int k, float z2r,
                                            const float* __restrict__ cb) {
    const float* zr = g_zf + (size_t)nrow*EDIM;
    const float* er = cb   + (size_t)k*EDIM;
    float s0 = 0.f, s1 = 0.f;
    #pragma unroll 8
    for (int d = 0; d < EDIM; d += 2) {
        s0 += zr[d]   * er[d];
        s1 += zr[d+1] * er[d+1];
    }
    return (z2r + g_e2[k]) - 2.f*(s0 + s1);
}

// ---------------------------------------------------------------------------
// Kernel A: transpose z (B, D, HWL) -> zf (B*HWL, D)
// ---------------------------------------------------------------------------
__global__ void vq_transpose(const float* __restrict__ z) {
    __shared__ float tile[32][33];
    int b = blockIdx.z, d0 = blockIdx.y << 5, s0 = blockIdx.x << 5;
    int tx = threadIdx.x, ty = threadIdx.y;
    const float* src = z + ((size_t)b*EDIM + d0)*HWL + s0;
    #pragma unroll
    for (int i = 0; i < 32; i += 8)
        tile[ty+i][tx] = src[(size_t)(ty+i)*HWL + tx];
    __syncthreads();
    float* dst = g_zf + ((size_t)b*HWL + s0)*EDIM + d0;
    #pragma unroll
    for (int i = 0; i < 32; i += 8)
        dst[(size_t)(ty+i)*EDIM + tx] = tile[tx][ty+i];
}

// ---------------------------------------------------------------------------
// Kernel B: codebook row norms (double accumulate -> correctly rounded fp32)
// ---------------------------------------------------------------------------
__global__ void vq_e2(const float* __restrict__ cb) {
    int k = blockIdx.x * blockDim.x + threadIdx.x;
    if (k < NEMB) {
        const float* row = cb + (size_t)k*EDIM;
        double s = 0.0;
        for (int d = 0; d < EDIM; d++) { double v = row[d]; s += v*v; }
        g_e2[k] = (float)s;
    }
}

// ---------------------------------------------------------------------------
// Kernel B2: pack codebook to fp16 ehat = 1024*e
// ---------------------------------------------------------------------------
__global__ __launch_bounds__(256)
void vq_packe(const float* __restrict__ cb) {
    int row = blockIdx.x*8 + (threadIdx.x >> 5);
    int lane = threadIdx.x & 31;
    const float* er = cb + (size_t)row*EDIM + lane*8;
    __half2 h[4];
    #pragma unroll
    for (int p = 0; p < 4; p++)
        h[p] = __floats2half2_rn(er[2*p]*1024.f, er[2*p+1]*1024.f);
    g_eh[row*32 + lane] = *(uint4*)h;
}

// ---------------------------------------------------------------------------
// Kernel B3: pack z rows to fp16 zhat = z/amax + per-row stats.
// 32 rows per block; ONLY t<64 do stats+pack (R9 OOB lesson).
// z2 order bit-matches the passing R2 pipeline (half sums, then add).
// ---------------------------------------------------------------------------
__global__ __launch_bounds__(256)
void vq_packz() {
    __shared__ float zt[32*257];
    int t = threadIdx.x;
    int rows = blockIdx.x * 32;
    for (int i = t; i < 32*64; i += 256) {
        int r = i >> 6, c4 = (i & 63) << 2;
        float4 v = *(const float4*)(g_zf + (size_t)(rows + r)*EDIM + c4);
        float* d = zt + r*257 + c4;
        d[0] = v.x; d[1] = v.y; d[2] = v.z; d[3] = v.w;
    }
    __syncthreads();
    if (t < 64) {
        int r = t >> 1, h = t & 1;
        int row = rows + r;
        const float* p = zt + r*257 + h*128;
        float s = 0.f, amax = 0.f;
        #pragma unroll 8
        for (int d = 0; d < 128; d++) {
            float v = p[d];
            s += v*v;
            amax = fmaxf(amax, fabsf(v));
        }
        float so = __shfl_xor_sync(0xffffffffu, s, 1);
        amax = fmaxf(amax, __shfl_xor_sync(0xffffffffu, amax, 1));
        if (!h) {
            g_z2[row] = s + so;                       // R2 ordering
            g_cr[row] = amax * (1.f/512.f);           // 2*amax/1024
            g_eps[row] = 0.025f*amax + 0.05f;         // >=2.5x worst-case fp16 bound
        }
        float scale = (amax > 0.f) ? (1.f/amax) : 0.f;
        #pragma unroll 4
        for (int wq = 0; wq < 16; wq++) {
            const float* q = p + wq*8;
            __half2 hh[4];
            #pragma unroll
            for (int k = 0; k < 4; k++)
                hh[k] = __floats2half2_rn(q[2*k]*scale, q[2*k+1]*scale);
            g_zh[row*32 + h*16 + wq] = *(uint4*)hh;
        }
    }
}

// ---------------------------------------------------------------------------
// B-chunk loader: 64 codes x 256 dims fp16, dim-major, pitch 65 uint4,
// INJECTIVE code placement: di = d8*65 + (c ^ ((c>>3)&7)).  (R12 bug fixed:
// additive skew wrapped at c=32 and collided; XOR form is a bijection.)
// Store: per warp c const, d8 = lane -> lane*65 mod 8 distinct, conflict-free;
// gmem src fully coalesced (512B per warp).
// ---------------------------------------------------------------------------
__device__ __forceinline__ void loadB(uint32_t sb, int cc, int t) {
    int buf = cc & 1;
    const uint4* src = g_eh + cc*64*32;
    uint32_t dst = sb + SM_B + buf*BBYTES;
    #pragma unroll
    for (int j = 0; j < 8; j++) {
        int i = t + j*256;                 // 0..2047
        int c = i >> 5, d8 = i & 31;
        int di = d8*65 + bpos(c);
        cpa16(dst + (uint32_t)di*16, src + c*32 + d8);
    }
    if (t < 64) cpa4(sb + SM_E2 + buf*256 + t*4, g_e2 + cc*64 + t);
    CP_COMMIT();
}

// ---------------------------------------------------------------------------
// Kernel C: fp16 HFMA2 GEMM + running-min screening + exact fp32 rescore
// 8 warps = 4 row-warps x 2 col-warps; warp 32 rows x 32 codes;
// lane = 4 row-groups x 8 code-groups; thread tile 8 rows x 4 codes.
// ---------------------------------------------------------------------------
__global__ __launch_bounds__(256, 1)
void vq_screen(const float* __restrict__ cb, float* __restrict__ out_idx, int write_idx) {
    extern __shared__ char smc[];
    uint32_t sb = smem_u32(smc);
    uint4* A4   = (uint4*)(smc + SM_A);
    float* z2s  = (float*)(smc + SM_Z2);
    float* crs  = (float*)(smc + SM_CR);
    float* epss = (float*)(smc + SM_EP);
    float* V    = (float*)(smc + SM_V);
    unsigned long long* best = (unsigned long long*)(smc + SM_BEST);
    unsigned* cand = (unsigned*)(smc + SM_CAND);
    int* scnt = (int*)(smc + SM_CNT);

    const int t = threadIdx.x, lane = t & 31, w = t >> 5;
    const int rw = w >> 1, cw = w & 1;
    const int rg = lane >> 3, cg = lane & 7;
    const int rowbase = rw*32 + rg*8;
    const int colbase = cw*32 + cg*4;              // within 64-code chunk
    const int n0 = blockIdx.x * MT;

    if (t < MT) {
        V[t] = 3.4e38f; V[MT + t] = 3.4e38f; best[t] = ~0ull;
        z2s[t]  = g_z2[n0 + t];
        crs[t]  = g_cr[n0 + t];
        epss[t] = g_eps[n0 + t];
    }
    if (t == 0) *scnt = 0;

    loadB(sb, 0, t);
    loadB(sb, 1, t);

    // A tile -> smem (skewed: row r data at r*36 + ((r>>3)&3), uint4 units)
    {
        const uint4* src = g_zh + (size_t)n0*32;
        for (int i = t; i < MT*32; i += 256) {
            int r = i >> 5, q = i & 31;
            A4[r*36 + ((r >> 3) & 3) + q] = src[r*32 + q];
        }
    }

    const int abase = rowbase*36 + rg;             // + i*36 + d8
    int bpx[4];
    #pragma unroll
    for (int j = 0; j < 4; j++) bpx[j] = bpos(colbase + j);

    for (int cc = 0; cc < NCHK; cc++) {
        int buf = cc & 1;
        if (cc + 1 < NCHK) CP_WAIT1(); else CP_WAIT0();
        __syncthreads();                           // covers init/A on cc==0 too

        const uint4* B4  = (const uint4*)(smc + SM_B + buf*BBYTES);
        const float* e2c = (const float*)(smc + SM_E2 + buf*256);

        float accf[8][4];
        #pragma unroll
        for (int i = 0; i < 8; i++)
            #pragma unroll
            for (int j = 0; j < 4; j++) accf[i][j] = 0.f;

        #pragma unroll 1
        for (int c4 = 0; c4 < 4; c4++) {           // 64-dim chunks (fp16 accum)
            __half2 acch[8][4];
            #pragma unroll
            for (int i = 0; i < 8; i++)
                #pragma unroll
                for (int j = 0; j < 4; j++) acch[i][j] = __float2half2_rn(0.f);
            #pragma unroll
            for (int d8l = 0; d8l < 8; d8l++) {
                int d8 = c4*8 + d8l;
                uint4 bv[4], av[8];
                #pragma unroll
                for (int j = 0; j < 4; j++) bv[j] = B4[d8*65 + bpx[j]];
                #pragma unroll
                for (int i = 0; i < 8; i++) av[i] = A4[abase + i*36 + d8];
                #pragma unroll
                for (int i = 0; i < 8; i++) {
                    const __half2* ah = (const __half2*)&av[i];
                    #pragma unroll
                    for (int j = 0; j < 4; j++) {
                        const __half2* bh = (const __half2*)&bv[j];
                        acch[i][j] = __hfma2(ah[0], bh[0], acch[i][j]);
                        acch[i][j] = __hfma2(ah[1], bh[1], acch[i][j]);
                        acch[i][j] = __hfma2(ah[2], bh[2], acch[i][j]);
                        acch[i][j] = __hfma2(ah[3], bh[3], acch[i][j]);
                    }
                }
            }
            #pragma unroll
            for (int i = 0; i < 8; i++)
                #pragma unroll
                for (int j = 0; j < 4; j++) {
                    float2 f = __half22float2(acch[i][j]);
                    accf[i][j] += f.x;
                    accf[i][j] += f.y;
                }
        }

        // 1) per-row chunk min -> update running min V (proven machinery)
        #pragma unroll
        for (int i = 0; i < 8; i++) {
            int row = rowbase + i;
            float z2r = z2s[row], cr = crs[row];
            float m = 3.4e38f;
            #pragma unroll
            for (int j = 0; j < 4; j++) {
                float dd = (z2r + e2c[colbase + j]) - accf[i][j]*cr;
                m = fminf(m, dd);
            }
            m = fminf(m, __shfl_down_sync(0xffffffffu, m, 4, 8));
            m = fminf(m, __shfl_down_sync(0xffffffffu, m, 2, 8));
            m = fminf(m, __shfl_down_sync(0xffffffffu, m, 1, 8));
            if (cg == 0) {
                float* vp = V + cw*MT + row;
                *vp = fminf(*vp, m);
            }
        }
        __syncwarp();
        // 2) candidate scan vs running min (+eps_r): superset of true argmin
        #pragma unroll
        for (int i = 0; i < 8; i++) {
            int row = rowbase + i;
            float z2r = z2s[row], cr = crs[row];
            float thr = fminf(V[row], V[MT + row]) + epss[row];
            #pragma unroll
            for (int j = 0; j < 4; j++) {
                float dd = (z2r + e2c[colbase + j]) - accf[i][j]*cr;
                if (dd <= thr) {
                    int k = cc*64 + colbase + j;
                    int idx = atomicAdd(scnt, 1);
                    if (idx < CAP) {
                        cand[idx] = ((unsigned)row << 16) | (unsigned)k;
                    } else {                      // overflow: exact inline (correct)
                        float de = exact_dist(n0 + row, k, z2r, cb);
                        unsigned long long key =
                            ((unsigned long long)__float_as_uint(de) << 32) | (unsigned)k;
                        atomicMin(best + row, key);
                    }
                }
            }
        }
        __syncthreads();                           // all reads of buf done before refill
        if (cc + 2 < NCHK) loadB(sb, cc + 2, t);
    }

    __syncthreads();
    // cooperative exact rescore (fp32 pipeline identical to passing kernels)
    int cnt = *scnt; if (cnt > CAP) cnt = CAP;
    for (int i = t; i < cnt; i += 256) {
        unsigned pk = cand[i];
        int row = (int)(pk >> 16), k = (int)(pk & 0xFFFFu);
        float de = exact_dist(n0 + row, k, z2s[row], cb);
        unsigned long long key = ((unsigned long long)__float_as_uint(de) << 32) | (unsigned)k;
        atomicMin(best + row, key);                // positive fp32 bit-monotonic; ties -> smaller k
    }
    __syncthreads();

    float* vmin = crs;                              // reuse
    if (t < MT) {
        unsigned long long kb = best[t];
        int k = (int)(kb & 0xFFFFFFFFull);
        g_idx[n0 + t] = k;
        if (write_idx) out_idx[n0 + t] = (float)k;
        vmin[t] = __uint_as_float((unsigned)(kb >> 32));
    }
    __syncthreads();
    if (t == 0) {
        double s = 0.0;
        for (int r = 0; r < MT; r++) s += (double)vmin[r];
        g_partial[blockIdx.x] = s;                  // deterministic
    }
}

// ---------------------------------------------------------------------------
// Kernel D: gather codebook rows by index, write (B, D, HWL)
// ---------------------------------------------------------------------------
__global__ __launch_bounds__(256)
void vq_scatter(const float* __restrict__ cb, float* __restrict__ outq) {
    __shared__ float qt[32*257];
    int b = blockIdx.y, s0 = blockIdx.x << 5, t = threadIdx.x;
    for (int i = t; i < 32*64; i += 256) {
        int r = i >> 6, c4 = i & 63;
        int k = g_idx[b*HWL + s0 + r];
        float4 v = *(const float4*)(cb + (size_t)k*EDIM + (c4 << 2));
        float* dst = qt + r*257 + (c4 << 2);
        dst[0] = v.x; dst[1] = v.y; dst[2] = v.z; dst[3] = v.w;
    }
    __syncthreads();
    int s = t & 31, dh = t >> 5;
    #pragma unroll
    for (int d = dh; d < EDIM; d += 8)
        outq[((size_t)b*EDIM + d)*HWL + s0 + s] = qt[s*257 + d];
}

// ---------------------------------------------------------------------------
// Kernel E: loss = 1.25 * sum(min_dist) / (N*D)
// ---------------------------------------------------------------------------
__global__ void vq_finalize(float* out_loss) {
    double s = 0.0;
    for (int i = 0; i < NBLK; i++) s += g_partial[i];
    *out_loss = (float)(1.25 * s / (double)((size_t)NROWS*EDIM));
}

// ---------------------------------------------------------------------------
extern "C" void kernel_launch(void* const* d_in, const int* in_sizes, int n_in,
                              void* d_out, int out_size) {
    const float* z  = (const float*)d_in[0];
    const float* cb = (const float*)d_in[1];
    if (n_in >= 2 && in_sizes[0] == NEMB*EDIM && in_sizes[1] == NROWS*EDIM) {
        const float* tmp = z; z = cb; cb = tmp;
    }
    float* out = (float*)d_out;

    const int QN = NROWS*EDIM;
    bool has_quant = (out_size >= QN);
    bool full      = (out_size == QN + NROWS + 1);
    float* out_idx  = full ? out + QN         : nullptr;
    float* out_loss = full ? out + QN + NROWS : nullptr;

    cudaFuncSetAttribute(vq_screen, cudaFuncAttributeMaxDynamicSharedMemorySize, SM_TOTAL);

    vq_transpose<<<dim3(HWL/32, EDIM/32, BATCH), dim3(32, 8)>>>(z);
    vq_e2<<<(NEMB + 255)/256, 256>>>(cb);
    vq_packe<<<NEMB/8, 256>>>(cb);
    vq_packz<<<NROWS/32, 256>>>();
    vq_screen<<<NBLK, 256, SM_TOTAL>>>(cb, out_idx, full ? 1 : 0);
    if (has_quant)
        vq_scatter<<<dim3(HWL/32, BATCH), 256>>>(cb, out);
    if (full)
        vq_finalize<<<1, 1>>>(out_loss);
}

// round 15
// speedup vs baseline: 25.2226x; 25.2226x over previous
#include <cuda_runtime.h>
#include <cuda_fp16.h>
#include <cstdint>
#include <cstddef>

// Problem constants
#define NEMB   1024
#define EDIM   256
#define BATCH  8
#define HWL    4096
#define NROWS  32768
#define MT     128
#define NBLK   256
#define NCB    8             // 8 code blocks of 128
#define CAP    4096

// smem byte offsets
#define SM_A     0           // 128 rows * 512 B (fp16, XOR-swizzled 16B units)
#define SM_B     65536       // 2 * 128 codes * 512 B
#define BBYTES   65536
#define SM_E2    196608      // 2*128 floats
#define SM_Z2    197632
#define SM_CR    198144
#define SM_EP    198656
#define SM_V     199168      // 2*128 floats
#define SM_BEST  200192      // 128 u64
#define SM_CAND  201216      // 4096 u32
#define SM_CNT   217600
#define SM_TOTAL 217616

// Scratch
__device__ float  g_zf[NROWS*EDIM];   // z transposed (N, D) fp32
__device__ uint4  g_zh[NROWS*32];     // fp16 zhat rows (32x16B = 256 dims)
__device__ uint4  g_eh[NEMB*32];      // fp16 ehat rows (e * 1024)
__device__ float  g_e2[NEMB];
__device__ float  g_z2[NROWS];
__device__ float  g_cr[NROWS];        // amax/512
__device__ float  g_eps[NROWS];       // HARD screening bound (tiny!)
__device__ int    g_idx[NROWS];
__device__ double g_partial[NBLK];

// ---------------- helpers ----------------
__device__ __forceinline__ uint32_t smem_u32(const void* p) {
    uint32_t a;
    asm("{ .reg .u64 t; cvta.to.shared.u64 t, %1; cvt.u32.u64 %0, t; }" : "=r"(a) : "l"(p));
    return a;
}
__device__ __forceinline__ void cpa16(uint32_t dst, const void* src) {
    asm volatile("cp.async.cg.shared.global [%0], [%1], 16;" :: "r"(dst), "l"(src));
}
__device__ __forceinline__ void cpa4(uint32_t dst, const void* src) {
    asm volatile("cp.async.ca.shared.global [%0], [%1], 4;" :: "r"(dst), "l"(src));
}
#define CP_COMMIT() asm volatile("cp.async.commit_group;" ::: "memory")
#define CP_WAIT1()  asm volatile("cp.async.wait_group 1;" ::: "memory")
#define CP_WAIT0()  asm volatile("cp.async.wait_group 0;" ::: "memory")

#define LDMX4(r0, r1, r2, r3, addr) \
    asm volatile("ldmatrix.sync.aligned.m8n8.x4.shared.b16 {%0,%1,%2,%3}, [%4];" \
        : "=r"(r0), "=r"(r1), "=r"(r2), "=r"(r3) : "r"(addr))

__device__ __forceinline__ void mma16816(float* d, const uint32_t* a, const uint32_t* b) {
    asm volatile("mma.sync.aligned.m16n8k16.row.col.f32.f16.f16.f32 "
        "{%0,%1,%2,%3}, {%4,%5,%6,%7}, {%8,%9}, {%0,%1,%2,%3};"
        : "+f"(d[0]), "+f"(d[1]), "+f"(d[2]), "+f"(d[3])
        : "r"(a[0]), "r"(a[1]), "r"(a[2]), "r"(a[3]), "r"(b[0]), "r"(b[1]));
}

// exact fp32 distance — IDENTICAL pipeline to the passing R2/R7/R11/R14 kernels
__device__ __forceinline__ float exact_dist(int nrow, int k, float z2r,
                                            const float* __restrict__ cb) {
    const float* zr = g_zf + (size_t)nrow*EDIM;
    const float* er = cb   + (size_t)k*EDIM;
    float s0 = 0.f, s1 = 0.f;
    #pragma unroll 8
    for (int d = 0; d < EDIM; d += 2) {
        s0 += zr[d]   * er[d];
        s1 += zr[d+1] * er[d+1];
    }
    return (z2r + g_e2[k]) - 2.f*(s0 + s1);
}

// ---------------------------------------------------------------------------
// Kernel A: transpose z (B, D, HWL) -> zf (B*HWL, D)
// ---------------------------------------------------------------------------
__global__ void vq_transpose(const float* __restrict__ z) {
    __shared__ float tile[32][33];
    int b = blockIdx.z, d0 = blockIdx.y << 5, s0 = blockIdx.x << 5;
    int tx = threadIdx.x, ty = threadIdx.y;
    const float* src = z + ((size_t)b*EDIM + d0)*HWL + s0;
    #pragma unroll
    for (int i = 0; i < 32; i += 8)
        tile[ty+i][tx] = src[(size_t)(ty+i)*HWL + tx];
    __syncthreads();
    float* dst = g_zf + ((size_t)b*HWL + s0)*EDIM + d0;
    #pragma unroll
    for (int i = 0; i < 32; i += 8)
        dst[(size_t)(ty+i)*EDIM + tx] = tile[tx][ty+i];
}

// ---------------------------------------------------------------------------
// Kernel B: codebook row norms (double accumulate -> correctly rounded fp32)
// ---------------------------------------------------------------------------
__global__ void vq_e2(const float* __restrict__ cb) {
    int k = blockIdx.x * blockDim.x + threadIdx.x;
    if (k < NEMB) {
        const float* row = cb + (size_t)k*EDIM;
        double s = 0.0;
        for (int d = 0; d < EDIM; d++) { double v = row[d]; s += v*v; }
        g_e2[k] = (float)s;
    }
}

// ---------------------------------------------------------------------------
// Kernel B2: pack codebook to fp16 ehat = 1024*e
// ---------------------------------------------------------------------------
__global__ __launch_bounds__(256)
void vq_packe(const float* __restrict__ cb) {
    int row = blockIdx.x*8 + (threadIdx.x >> 5);
    int lane = threadIdx.x & 31;
    const float* er = cb + (size_t)row*EDIM + lane*8;
    __half2 h[4];
    #pragma unroll
    for (int p = 0; p < 4; p++)
        h[p] = __floats2half2_rn(er[2*p]*1024.f, er[2*p+1]*1024.f);
    g_eh[row*32 + lane] = *(uint4*)h;
}

// ---------------------------------------------------------------------------
// Kernel B3: pack z rows to fp16 zhat = z/amax + per-row stats (proven R14,
// eps formula replaced by the rigorous fp16-mma bound).
// ---------------------------------------------------------------------------
__global__ __launch_bounds__(256)
void vq_packz() {
    __shared__ float zt[32*257];
    int t = threadIdx.x;
    int rows = blockIdx.x * 32;
    for (int i = t; i < 32*64; i += 256) {
        int r = i >> 6, c4 = (i & 63) << 2;
        float4 v = *(const float4*)(g_zf + (size_t)(rows + r)*EDIM + c4);
        float* d = zt + r*257 + c4;
        d[0] = v.x; d[1] = v.y; d[2] = v.z; d[3] = v.w;
    }
    __syncthreads();
    if (t < 64) {
        int r = t >> 1, h = t & 1;
        int row = rows + r;
        const float* p = zt + r*257 + h*128;
        float s = 0.f, amax = 0.f;
        #pragma unroll 8
        for (int d = 0; d < 128; d++) {
            float v = p[d];
            s += v*v;
            amax = fmaxf(amax, fabsf(v));
        }
        float so = __shfl_xor_sync(0xffffffffu, s, 1);
        amax = fmaxf(amax, __shfl_xor_sync(0xffffffffu, amax, 1));
        if (!h) {
            float z2 = s + so;                        // R2 ordering
            g_z2[row] = z2;
            g_cr[row] = amax * (1.f/512.f);           // 2*amax/1024
            // HARD bound: 2*(quant err 2^-10*||zhat||*||ehat||*cr + accum) + slack
            g_eps[row] = sqrtf(z2)*6.3e-5f + amax*4e-5f + 2e-4f;
        }
        float scale = (amax > 0.f) ? (1.f/amax) : 0.f;
        #pragma unroll 4
        for (int wq = 0; wq < 16; wq++) {
            const float* q = p + wq*8;
            __half2 hh[4];
            #pragma unroll
            for (int k = 0; k < 4; k++)
                hh[k] = __floats2half2_rn(q[2*k]*scale, q[2*k+1]*scale);
            g_zh[row*32 + h*16 + wq] = *(uint4*)hh;
        }
    }
}

// ---------------------------------------------------------------------------
// Stagers: rows of 512B = 32 16B-units; unit u of row r stored at u ^ (r&7).
// cp.async: warp writes one row's 32 units -> per 128B phase units distinct. OK
// ---------------------------------------------------------------------------
__device__ __forceinline__ void stageA(uint32_t sb, int n0, int t) {
    const uint4* src = g_zh + (size_t)n0*32;
    #pragma unroll
    for (int j = 0; j < 16; j++) {
        int i = t + j*256;                 // 0..4095
        int r = i >> 5, u = i & 31;
        cpa16(sb + SM_A + (uint32_t)(r*512 + ((u ^ (r & 7)) << 4)), src + r*32 + u);
    }
}
__device__ __forceinline__ void loadB(uint32_t sb, int cb, int t) {
    int buf = cb & 1;
    const uint4* src = g_eh + cb*128*32;
    uint32_t dst = sb + SM_B + buf*BBYTES;
    #pragma unroll
    for (int j = 0; j < 16; j++) {
        int i = t + j*256;                 // 0..4095
        int r = i >> 5, u = i & 31;
        cpa16(dst + (uint32_t)(r*512 + ((u ^ (r & 7)) << 4)), src + r*32 + u);
    }
    if (t < 128) cpa4(sb + SM_E2 + buf*512 + t*4, g_e2 + cb*128 + t);
    CP_COMMIT();
}

// ---------------------------------------------------------------------------
// Kernel C: fp16 mma.sync (m16n8k16, fp32 acc) + running-min screening +
// exact fp32 rescore.  8 warps = 4 row x 2 col; warp tile 32 rows x 64 codes.
// ---------------------------------------------------------------------------
__global__ __launch_bounds__(256, 1)
void vq_screen(const float* __restrict__ cb, float* __restrict__ out_idx, int write_idx) {
    extern __shared__ char smc[];
    uint32_t sb = smem_u32(smc);
    float* z2s  = (float*)(smc + SM_Z2);
    float* crs  = (float*)(smc + SM_CR);
    float* epss = (float*)(smc + SM_EP);
    float* V    = (float*)(smc + SM_V);
    unsigned long long* best = (unsigned long long*)(smc + SM_BEST);
    unsigned* cand = (unsigned*)(smc + SM_CAND);
    int* scnt = (int*)(smc + SM_CNT);

    const int t = threadIdx.x, lane = t & 31, w = t >> 5;
    const int rw = w >> 1, cw = w & 1;
    const int la = lane & 7;
    const int g  = lane >> 2, q = lane & 3;
    const int n0 = blockIdx.x * MT;

    if (t < MT) {
        V[t] = 3.4e38f; V[MT + t] = 3.4e38f; best[t] = ~0ull;
        z2s[t]  = g_z2[n0 + t];
        crs[t]  = g_cr[n0 + t];
        epss[t] = g_eps[n0 + t];
    }
    if (t == 0) *scnt = 0;

    stageA(sb, n0, t);
    loadB(sb, 0, t);       // group0 = A + B0 + e2_0
    loadB(sb, 1, t);       // group1 = B1 + e2_1

    // ldmatrix per-lane geometry (matches PTX m8n8.x4 fragment/address tables)
    const int m4   = lane >> 3;                    // matrix index 0..3
    const int arow = rw*32 + (m4 & 1)*8 + la;      // A: m0 r0-7 u0, m1 r8-15 u0, m2 r0-7 u1, m3 r8-15 u1
    const int auo  = m4 >> 1;
    const int bco  = ((m4 >> 1) & 1)*8 + la;       // B: m0 c0-7 u0, m1 c0-7 u1, m2 c+8 u0, m3 c+8 u1
    const int buo  = m4 & 1;
    const uint32_t aAbase = sb + SM_A + (uint32_t)arow*512;

    for (int cbk = 0; cbk < NCB; cbk++) {
        int buf = cbk & 1;
        if (cbk + 1 < NCB) CP_WAIT1(); else CP_WAIT0();
        __syncthreads();

        const uint32_t bBbase = sb + SM_B + buf*BBYTES;
        const float* e2c = (const float*)(smc + SM_E2 + buf*512);

        float d[2][8][4];
        #pragma unroll
        for (int mr = 0; mr < 2; mr++)
            #pragma unroll
            for (int nc = 0; nc < 8; nc++)
                #pragma unroll
                for (int u = 0; u < 4; u++) d[mr][nc][u] = 0.f;

        #pragma unroll 4
        for (int ks = 0; ks < 16; ks++) {
            uint32_t a[2][4], b[8][2];
            #pragma unroll
            for (int mr = 0; mr < 2; mr++) {
                uint32_t addr = aAbase + mr*16*512 + (uint32_t)(((2*ks + auo) ^ la) << 4);
                LDMX4(a[mr][0], a[mr][1], a[mr][2], a[mr][3], addr);
            }
            #pragma unroll
            for (int p = 0; p < 4; p++) {
                int code = cw*64 + p*16 + bco;
                uint32_t addr = bBbase + (uint32_t)code*512 + (uint32_t)(((2*ks + buo) ^ la) << 4);
                uint32_t r0, r1, r2, r3;
                LDMX4(r0, r1, r2, r3, addr);
                b[2*p][0] = r0;   b[2*p][1] = r1;     // n-block p*2:   k0-7, k8-15
                b[2*p+1][0] = r2; b[2*p+1][1] = r3;   // n-block p*2+1
            }
            #pragma unroll
            for (int mr = 0; mr < 2; mr++)
                #pragma unroll
                for (int nc = 0; nc < 8; nc++)
                    mma16816(d[mr][nc], a[mr], b[nc]);
        }

        // scoring: D element (mr,nc): rows rw*32+mr*16+{g, g+8}, cols nc*8+2q+{0,1}
        #pragma unroll
        for (int mr = 0; mr < 2; mr++)
            #pragma unroll
            for (int h = 0; h < 2; h++) {
                int row = rw*32 + mr*16 + h*8 + g;
                float z2r = z2s[row], cr = crs[row];
                float m = 3.4e38f;
                #pragma unroll
                for (int nc = 0; nc < 8; nc++) {
                    int col = cw*64 + nc*8 + 2*q;
                    float d0 = (z2r + e2c[col])   - d[mr][nc][2*h]*cr;
                    float d1 = (z2r + e2c[col+1]) - d[mr][nc][2*h+1]*cr;
                    m = fminf(m, fminf(d0, d1));
                }
                m = fminf(m, __shfl_xor_sync(0xffffffffu, m, 1));
                m = fminf(m, __shfl_xor_sync(0xffffffffu, m, 2));
                if (q == 0) {
                    float* vp = V + cw*MT + row;
                    *vp = fminf(*vp, m);
                }
            }
        __syncwarp();
        #pragma unroll
        for (int mr = 0; mr < 2; mr++)
            #pragma unroll
            for (int h = 0; h < 2; h++) {
                int row = rw*32 + mr*16 + h*8 + g;
                float z2r = z2s[row], cr = crs[row];
                float thr = fminf(V[row], V[MT + row]) + epss[row];
                #pragma unroll
                for (int nc = 0; nc < 8; nc++)
                    #pragma unroll
                    for (int c01 = 0; c01 < 2; c01++) {
                        int col = cw*64 + nc*8 + 2*q + c01;
                        float dd = (z2r + e2c[col]) - d[mr][nc][2*h+c01]*cr;
                        if (dd <= thr) {
                            int k = cbk*MT + col;
                            int idx = atomicAdd(scnt, 1);
                            if (idx < CAP) {
                                cand[idx] = ((unsigned)row << 16) | (unsigned)k;
                            } else {            // overflow: exact inline (correct, rare)
                                float de = exact_dist(n0 + row, k, z2r, cb);
                                unsigned long long key =
                                    ((unsigned long long)__float_as_uint(de) << 32) | (unsigned)k;
                                atomicMin(best + row, key);
                            }
                        }
                    }
            }
        __syncthreads();
        if (cbk + 2 < NCB) loadB(sb, cbk + 2, t);
    }

    __syncthreads();
    // cooperative exact rescore (proven fp32 pipeline)
    int cnt = *scnt; if (cnt > CAP) cnt = CAP;
    for (int i = t; i < cnt; i += 256) {
        unsigned pk = cand[i];
        int row = (int)(pk >> 16), k = (int)(pk & 0xFFFFu);
        float de = exact_dist(n0 + row, k, z2s[row], cb);
        unsigned long long key = ((unsigned long long)__float_as_uint(de) << 32) | (unsigned)k;
        atomicMin(best + row, key);            // positive fp32 bit-monotonic; ties -> smaller k
    }
    __syncthreads();

    float* vmin = crs;                          // reuse
    if (t < MT) {
        unsigned long long kb = best[t];
        int k = (int)(kb & 0xFFFFFFFFull);
        g_idx[n0 + t] = k;
        if (write_idx) out_idx[n0 + t] = (float)k;
        vmin[t] = __uint_as_float((unsigned)(kb >> 32));
    }
    __syncthreads();
    if (t == 0) {
        double s = 0.0;
        for (int r = 0; r < MT; r++) s += (double)vmin[r];
        g_partial[blockIdx.x] = s;              // deterministic
    }
}

// ---------------------------------------------------------------------------
// Kernel D: gather codebook rows by index, write (B, D, HWL)
// ---------------------------------------------------------------------------
__global__ __launch_bounds__(256)
void vq_scatter(const float* __restrict__ cb, float* __restrict__ outq) {
    __shared__ float qt[32*257];
    int b = blockIdx.y, s0 = blockIdx.x << 5, t = threadIdx.x;
    for (int i = t; i < 32*64; i += 256) {
        int r = i >> 6, c4 = i & 63;
        int k = g_idx[b*HWL + s0 + r];
        float4 v = *(const float4*)(cb + (size_t)k*EDIM + (c4 << 2));
        float* dst = qt + r*257 + (c4 << 2);
        dst[0] = v.x; dst[1] = v.y; dst[2] = v.z; dst[3] = v.w;
    }
    __syncthreads();
    int s = t & 31, dh = t >> 5;
    #pragma unroll
    for (int d = dh; d < EDIM; d += 8)
        outq[((size_t)b*EDIM + d)*HWL + s0 + s] = qt[s*257 + d];
}

// ---------------------------------------------------------------------------
// Kernel E: loss = 1.25 * sum(min_dist) / (N*D)
// ---------------------------------------------------------------------------
__global__ void vq_finalize(float* out_loss) {
    double s = 0.0;
    for (int i = 0; i < NBLK; i++) s += g_partial[i];
    *out_loss = (float)(1.25 * s / (double)((size_t)NROWS*EDIM));
}

// ---------------------------------------------------------------------------
extern "C" void kernel_launch(void* const* d_in, const int* in_sizes, int n_in,
                              void* d_out, int out_size) {
    const float* z  = (const float*)d_in[0];
    const float* cb = (const float*)d_in[1];
    if (n_in >= 2 && in_sizes[0] == NEMB*EDIM && in_sizes[1] == NROWS*EDIM) {
        const float* tmp = z; z = cb; cb = tmp;
    }
    float* out = (float*)d_out;

    const int QN = NROWS*EDIM;
    bool has_quant = (out_size >= QN);
    bool full      = (out_size == QN + NROWS + 1);
    float* out_idx  = full ? out + QN         : nullptr;
    float* out_loss = full ? out + QN + NROWS : nullptr;

    cudaFuncSetAttribute(vq_screen, cudaFuncAttributeMaxDynamicSharedMemorySize, SM_TOTAL);

    vq_transpose<<<dim3(HWL/32, EDIM/32, BATCH), dim3(32, 8)>>>(z);
    vq_e2<<<(NEMB + 255)/256, 256>>>(cb);
    vq_packe<<<NEMB/8, 256>>>(cb);
    vq_packz<<<NROWS/32, 256>>>();
    vq_screen<<<NBLK, 256, SM_TOTAL>>>(cb, out_idx, full ? 1 : 0);
    if (has_quant)
        vq_scatter<<<dim3(HWL/32, BATCH), 256>>>(cb, out);
    if (full)
        vq_finalize<<<1, 1>>>(out_loss);
}